// round 1
// baseline (speedup 1.0000x reference)
#include <cuda_runtime.h>
#include <stdint.h>

#define BB 1024
#define TT 1024
#define KK 48
#define START_TAG 46
#define STOP_TAG 47
#define NEGV (-10000.0f)
#define SPB 7                 // sequences per block
#define NTHREADS (SPB * KK)   // 336
#define WIN 64                // backtrack window (rows staged in smem)

// backpointer scratch: [t][seq][next], uint8 (prev tag in 0..47)
__device__ __align__(16) uint8_t g_bptr[(size_t)TT * BB * KK];

__global__ __launch_bounds__(NTHREADS, 1)
void viterbi_kernel(const float* __restrict__ feats,
                    const float* __restrict__ trans,
                    float* __restrict__ out)
{
    __shared__ __align__(16) float fv_sh[2][SPB][KK];
    __shared__ float term_sh[SPB][KK];
    __shared__ int   bestTag_sh[SPB];
    __shared__ __align__(16) uint8_t win_sh[SPB][WIN][KK];

    const int tid = threadIdx.x;
    const int g   = tid / KK;        // group (sequence slot) 0..6
    const int n   = tid % KK;        // 'next' tag 0..47
    const int seq = blockIdx.x * SPB + g;
    const bool active = (seq < BB);
    const int seqc = active ? seq : (BB - 1);   // clamped for safe loads

    // Transition row for this 'next' tag stays in registers for all T steps.
    float tr[KK];
#pragma unroll
    for (int p = 0; p < KK; p++) tr[p] = trans[n * KK + p];
    const float trStop = trans[STOP_TAG * KK + n];

    // init forward var
    fv_sh[0][g][n] = (n == START_TAG) ? 0.0f : NEGV;
    __syncthreads();

    const float* fbase = feats + (size_t)seqc * TT * KK + n;
    float feat_next = fbase[0];

    int buf = 0;
    for (int t = 0; t < TT; t++) {
        const float feat = feat_next;
        if (t + 1 < TT) feat_next = fbase[(size_t)(t + 1) * KK];

        const float4* fvr = reinterpret_cast<const float4*>(&fv_sh[buf][g][0]);

        // 4 independent compare chains (strict > keeps first occurrence within chain)
        float4 v = fvr[0];
        float b0 = v.x + tr[0]; int i0 = 0;
        float b1 = v.y + tr[1]; int i1 = 1;
        float b2 = v.z + tr[2]; int i2 = 2;
        float b3 = v.w + tr[3]; int i3 = 3;
#pragma unroll
        for (int j = 1; j < KK / 4; j++) {
            float4 w = fvr[j];
            float s0 = w.x + tr[4*j+0]; if (s0 > b0) { b0 = s0; i0 = 4*j+0; }
            float s1 = w.y + tr[4*j+1]; if (s1 > b1) { b1 = s1; i1 = 4*j+1; }
            float s2 = w.z + tr[4*j+2]; if (s2 > b2) { b2 = s2; i2 = 4*j+2; }
            float s3 = w.w + tr[4*j+3]; if (s3 > b3) { b3 = s3; i3 = 4*j+3; }
        }
        // exact lexicographic combine: larger value wins; on equal value, smaller index
        if (b1 > b0 || (b1 == b0 && i1 < i0)) { b0 = b1; i0 = i1; }
        if (b3 > b2 || (b3 == b2 && i3 < i2)) { b2 = b3; i2 = i3; }
        if (b2 > b0 || (b2 == b0 && i2 < i0)) { b0 = b2; i0 = i2; }

        const float newfv = b0 + feat;
        fv_sh[buf ^ 1][g][n] = newfv;
        if (active)
            g_bptr[(size_t)t * (BB * KK) + (size_t)seq * KK + n] = (uint8_t)i0;
        __syncthreads();
        buf ^= 1;
    }

    // terminal = fv + transitions[STOP] row
    term_sh[g][n] = fv_sh[buf][g][n] + trStop;
    __syncthreads();
    if (n == 0 && active) {
        float best = term_sh[g][0]; int bi = 0;
#pragma unroll
        for (int p = 1; p < KK; p++) {
            float v2 = term_sh[g][p];
            if (v2 > best) { best = v2; bi = p; }
        }
        out[seq] = best;          // path_score
        bestTag_sh[g] = bi;
    }
    __syncthreads();

    // ---- windowed backtrack ----
    float* pout = out + BB + (size_t)seqc * TT;
    int tag = bestTag_sh[g];      // meaningful on thread n==0 of active groups
    const int ROW_U4 = (BB * KK) / 16;  // 3072 uint4 between consecutive t-rows

    for (int t0 = TT - WIN; t0 >= 0; t0 -= WIN) {
        // cooperative coalesced load of WIN rows (48B each) into smem
        const uint4* src = reinterpret_cast<const uint4*>(
            g_bptr + (size_t)t0 * (BB * KK) + (size_t)seqc * KK);
        uint4* dst = reinterpret_cast<uint4*>(&win_sh[g][0][0]);
#pragma unroll
        for (int k = 0; k < (WIN * 3) / KK; k++) {   // 192 uint4 / 48 threads = 4 each
            int idx  = n + k * KK;                   // 0..191
            int row  = idx / 3;
            int word = idx % 3;
            dst[idx] = src[(size_t)row * ROW_U4 + word];
        }
        __syncthreads();
        if (n == 0 && active) {
            for (int t = t0 + WIN - 1; t >= t0; t--) {
                pout[t] = (float)tag;
                tag = win_sh[g][t - t0][tag];
            }
        }
        __syncthreads();
    }
}

extern "C" void kernel_launch(void* const* d_in, const int* in_sizes, int n_in,
                              void* d_out, int out_size) {
    (void)in_sizes; (void)n_in; (void)out_size;
    const float* feats = (const float*)d_in[0];
    const float* trans = (const float*)d_in[1];
    float* out = (float*)d_out;
    dim3 grid((BB + SPB - 1) / SPB);
    viterbi_kernel<<<grid, NTHREADS>>>(feats, trans, out);
}

// round 2
// speedup vs baseline: 1.3224x; 1.3224x over previous
#include <cuda_runtime.h>
#include <stdint.h>

#define BB 1024
#define TT 1024
#define KK 48
#define START_TAG 46
#define STOP_TAG 47
#define NEGV (-10000.0f)
#define PADV (-3.0e38f)
#define SPB 7                  // sequences per block
#define TPS 96                 // threads per sequence (2 per 'next' tag)
#define NTHREADS (SPB * TPS)   // 672

// forward-variable scratch: [t][seq][tag] floats (row t = fv BEFORE step t)
__device__ __align__(16) float g_fv[(size_t)TT * BB * KK];

// exact lexicographic warp argmax over 48 candidates (value desc, index asc on ties)
__device__ __forceinline__ void argmax48(float sa, int ia, float sb, int ib,
                                         float& v_out, int& i_out) {
    bool tk = (sb > sa);                 // strict: tie keeps lower index (ia < ib)
    float v = tk ? sb : sa;
    int   i = tk ? ib : ia;
#pragma unroll
    for (int m = 16; m >= 1; m >>= 1) {
        float ov = __shfl_xor_sync(0xffffffffu, v, m);
        int   oi = __shfl_xor_sync(0xffffffffu, i, m);
        bool take = (ov > v) || (ov == v && oi < i);
        v = take ? ov : v;
        i = take ? oi : i;
    }
    v_out = v; i_out = i;
}

__global__ __launch_bounds__(NTHREADS, 1)
void viterbi_kernel(const float* __restrict__ feats,
                    const float* __restrict__ trans,
                    float* __restrict__ out)
{
    __shared__ __align__(16) float fv_sh[2][SPB][KK];
    __shared__ float trans_sh[KK * KK];
    __shared__ uint8_t path_sh[SPB][TT];

    const int tid = threadIdx.x;
    const int g   = tid / TPS;       // sequence slot 0..6
    const int j   = tid % TPS;       // 0..95
    const int n   = j >> 1;          // 'next' tag 0..47
    const int c   = j & 1;           // half: prevs [c*24, c*24+24)
    const int seq = blockIdx.x * SPB + g;
    const bool active = (seq < BB);
    const int seqc = active ? seq : (BB - 1);

    // stage transitions into smem (used by backtrack)
    for (int i2 = tid; i2 < KK * KK; i2 += NTHREADS) trans_sh[i2] = trans[i2];

    // this thread's 24 transition entries stay in registers
    float tr[24];
#pragma unroll
    for (int k = 0; k < 24; k++) tr[k] = trans[n * KK + c * 24 + k];

    if (c == 0) fv_sh[0][g][n] = (n == START_TAG) ? 0.0f : NEGV;
    __syncthreads();

    const float* fbase = feats + (size_t)seqc * TT * KK + n;
    float feat_next = fbase[0];
    float* sbase = g_fv + (size_t)seqc * KK + n;   // + t*BB*KK

    // ---------------- forward pass: max-only (no argmax) ----------------
    int buf = 0;
#pragma unroll 2
    for (int t = 0; t < TT; t++) {
        float feat = feat_next;
        if (t + 1 < TT) feat_next = fbase[(size_t)(t + 1) * KK];

        const float4* fvr = reinterpret_cast<const float4*>(&fv_sh[buf][g][c * 24]);
        float4 v0 = fvr[0];
        float b0 = v0.x + tr[0], b1 = v0.y + tr[1];
        float b2 = v0.z + tr[2], b3 = v0.w + tr[3];
#pragma unroll
        for (int q = 1; q < 6; q++) {
            float4 w = fvr[q];
            b0 = fmaxf(b0, w.x + tr[4 * q + 0]);
            b1 = fmaxf(b1, w.y + tr[4 * q + 1]);
            b2 = fmaxf(b2, w.z + tr[4 * q + 2]);
            b3 = fmaxf(b3, w.w + tr[4 * q + 3]);
        }
        float b = fmaxf(fmaxf(b0, b1), fmaxf(b2, b3));
        b = fmaxf(b, __shfl_xor_sync(0xffffffffu, b, 1));   // combine halves
        float newfv = b + feat;
        if (c == 0) {
            fv_sh[buf ^ 1][g][n] = newfv;
            if (active && t + 1 < TT)
                sbase[(size_t)(t + 1) * (BB * KK)] = newfv;  // row t+1 = fv before step t+1
        }
        __syncthreads();
        buf ^= 1;
    }

    // ---------------- terminal + backtrack (warp per sequence) ----------------
    if (j < 32 && active) {
        const int l = j;
        // terminal = fv_final + trans[STOP] row
        float fa = fv_sh[buf][g][l];
        float fb = (l < 16) ? fv_sh[buf][g][32 + l] : 0.0f;
        float sa = fa + trans_sh[STOP_TAG * KK + l];
        float sb = (l < 16) ? (fb + trans_sh[STOP_TAG * KK + 32 + l]) : PADV;
        float best; int tag;
        argmax48(sa, l, sb, 32 + l, best, tag);
        if (l == 0) out[seq] = best;

        const float* rowbase = g_fv + (size_t)seq * KK;
        const size_t RSTR = (size_t)BB * KK;
        // 3-deep register prefetch pipeline of fv rows (hides DRAM latency)
        float a0 = rowbase[(size_t)(TT - 1) * RSTR + l];
        float e0 = (l < 16) ? rowbase[(size_t)(TT - 1) * RSTR + 32 + l] : 0.0f;
        float a1 = rowbase[(size_t)(TT - 2) * RSTR + l];
        float e1 = (l < 16) ? rowbase[(size_t)(TT - 2) * RSTR + 32 + l] : 0.0f;
        float a2 = rowbase[(size_t)(TT - 3) * RSTR + l];
        float e2 = (l < 16) ? rowbase[(size_t)(TT - 3) * RSTR + 32 + l] : 0.0f;

#define BT_STEP(T_, AA, EE, PF)                                              \
        {                                                                    \
            if (l == 0) path_sh[g][(T_)] = (uint8_t)tag;                     \
            float s_a = AA + trans_sh[tag * KK + l];                         \
            float s_b = (l < 16) ? (EE + trans_sh[tag * KK + 32 + l]) : PADV;\
            int rpf = ((PF) < 1) ? 1 : (PF);                                 \
            AA = rowbase[(size_t)rpf * RSTR + l];                            \
            EE = (l < 16) ? rowbase[(size_t)rpf * RSTR + 32 + l] : 0.0f;     \
            float bv; int bi;                                                \
            argmax48(s_a, l, s_b, 32 + l, bv, bi);                           \
            tag = bi;                                                        \
        }

        // steps t = TT-1 .. 1 (1023 steps, divisible by 3)
        for (int t = TT - 1; t >= 3; t -= 3) {
            BT_STEP(t,     a0, e0, t - 3)
            BT_STEP(t - 1, a1, e1, t - 4)
            BT_STEP(t - 2, a2, e2, t - 5)
        }
        if (l == 0) path_sh[g][0] = (uint8_t)tag;
#undef BT_STEP
    }
    __syncthreads();

    // ---------------- coalesced path dump ----------------
    for (int idx = tid; idx < SPB * TT; idx += NTHREADS) {
        int gg = idx >> 10;
        int t  = idx & (TT - 1);
        int s2 = blockIdx.x * SPB + gg;
        if (s2 < BB) out[BB + (size_t)s2 * TT + t] = (float)path_sh[gg][t];
    }
}

extern "C" void kernel_launch(void* const* d_in, const int* in_sizes, int n_in,
                              void* d_out, int out_size) {
    (void)in_sizes; (void)n_in; (void)out_size;
    const float* feats = (const float*)d_in[0];
    const float* trans = (const float*)d_in[1];
    float* out = (float*)d_out;
    dim3 grid((BB + SPB - 1) / SPB);
    viterbi_kernel<<<grid, NTHREADS>>>(feats, trans, out);
}

// round 5
// speedup vs baseline: 1.8950x; 1.4330x over previous
#include <cuda_runtime.h>
#include <stdint.h>

#define BB 1024
#define TT 1024
#define KK 48
#define START_TAG 46
#define STOP_TAG 47
#define NEGV (-10000.0f)
#define PADV (-3.0e38f)
#define NT 96                  // one sequence per block: 2 threads per 'next' tag

// forward-variable scratch: [t][seq][tag] (row t = fv BEFORE step t), +1 pad row
__device__ __align__(16) float g_fv[(size_t)(TT + 1) * BB * KK];

// monotone float -> ordered signed int (exact for all non-NaN floats)
__device__ __forceinline__ int fkey(float f) {
    int i = __float_as_int(f);
    return (i >= 0) ? i : (i ^ 0x7fffffff);
}

// exact argmax over 48 candidates distributed as: lane l holds index l (sa)
// and index 32+l (sb; PADV for l>=16). Ties -> lowest index (matches jnp.argmax).
__device__ __forceinline__ int argmax48(float sa, float sb, float* bout) {
    int ka = fkey(sa), kb = fkey(sb);
    int v = (ka > kb) ? ka : kb;
    int m;
    asm("redux.sync.max.s32 %0, %1, 0xffffffff;" : "=r"(m) : "r"(v));
    unsigned ba = __ballot_sync(0xffffffffu, ka == m);
    unsigned bb = __ballot_sync(0xffffffffu, kb == m);
    int idx = ba ? (__ffs((int)ba) - 1) : (31 + __ffs((int)bb));
    // recover float max from key
    int mi = (m >= 0) ? m : (m ^ 0x7fffffff);
    *bout = __int_as_float(mi);
    return idx;
}

__global__ __launch_bounds__(NT)
void viterbi_kernel(const float* __restrict__ feats,
                    const float* __restrict__ trans,
                    float* __restrict__ out)
{
    __shared__ __align__(16) float fv_sh[2][KK];
    __shared__ __align__(16) float trans_sh[KK * KK];
    __shared__ uint8_t path_sh[TT];

    const int tid = threadIdx.x;
    const int n   = tid >> 1;        // 'next' tag 0..47
    const int c   = tid & 1;         // half: prevs [c*24, c*24+24)
    const int seq = blockIdx.x;      // grid == BB

    // stage transitions into smem (used only by backtrack)
    for (int i2 = tid; i2 < KK * KK; i2 += NT) trans_sh[i2] = trans[i2];

    // this thread's 24 transition entries live in registers all T steps
    float tr[24];
#pragma unroll
    for (int k = 0; k < 24; k++) tr[k] = trans[n * KK + c * 24 + k];

    if (c == 0) fv_sh[0][n] = (n == START_TAG) ? 0.0f : NEGV;
    __syncthreads();

    const float* fbase = feats + (size_t)seq * TT * KK + n;
    float feat_next = fbase[0];
    float* sbase = g_fv + (size_t)seq * KK + n;      // + t*BB*KK

    // ---------------- forward pass: max-only ----------------
    int buf = 0;
#pragma unroll 4
    for (int t = 0; t < TT; t++) {
        float feat = feat_next;
        int tn = (t + 1 < TT) ? (t + 1) : (TT - 1);  // clamped prefetch
        feat_next = fbase[(size_t)tn * KK];

        const float4* fvr = reinterpret_cast<const float4*>(&fv_sh[buf][c * 24]);
        float4 v0 = fvr[0];
        float b0 = v0.x + tr[0], b1 = v0.y + tr[1];
        float b2 = v0.z + tr[2], b3 = v0.w + tr[3];
#pragma unroll
        for (int q = 1; q < 6; q++) {
            float4 w = fvr[q];
            b0 = fmaxf(b0, w.x + tr[4 * q + 0]);
            b1 = fmaxf(b1, w.y + tr[4 * q + 1]);
            b2 = fmaxf(b2, w.z + tr[4 * q + 2]);
            b3 = fmaxf(b3, w.w + tr[4 * q + 3]);
        }
        float b = fmaxf(fmaxf(b0, b1), fmaxf(b2, b3));
        b = fmaxf(b, __shfl_xor_sync(0xffffffffu, b, 1));   // combine halves
        float newfv = b + feat;
        if (c == 0) {
            fv_sh[buf ^ 1][n] = newfv;
            sbase[(size_t)(t + 1) * (BB * KK)] = newfv;     // row t+1 (padded)
        }
        __syncthreads();
        buf ^= 1;
    }

    // ---------------- terminal + backtrack (warp 0) ----------------
    if (tid < 32) {
        const int l = tid;
        float fa = fv_sh[buf][l];
        float fb = (l < 16) ? fv_sh[buf][32 + l] : 0.0f;
        float sa = fa + trans_sh[STOP_TAG * KK + l];
        float sb = (l < 16) ? (fb + trans_sh[STOP_TAG * KK + 32 + l]) : PADV;
        float best;
        int tag = argmax48(sa, sb, &best);
        if (l == 0) out[seq] = best;

        const float* rowbase = g_fv + (size_t)seq * KK;
        const size_t RSTR = (size_t)BB * KK;
        // 3-deep register prefetch of fv rows hides DRAM/L2 latency
        float a0 = rowbase[(size_t)(TT - 1) * RSTR + l];
        float e0 = (l < 16) ? rowbase[(size_t)(TT - 1) * RSTR + 32 + l] : 0.0f;
        float a1 = rowbase[(size_t)(TT - 2) * RSTR + l];
        float e1 = (l < 16) ? rowbase[(size_t)(TT - 2) * RSTR + 32 + l] : 0.0f;
        float a2 = rowbase[(size_t)(TT - 3) * RSTR + l];
        float e2 = (l < 16) ? rowbase[(size_t)(TT - 3) * RSTR + 32 + l] : 0.0f;

#define BT_STEP(T_, AA, EE, PF)                                              \
        {                                                                    \
            if (l == 0) path_sh[(T_)] = (uint8_t)tag;                        \
            float s_a = AA + trans_sh[tag * KK + l];                         \
            float s_b = (l < 16) ? (EE + trans_sh[tag * KK + 32 + l]) : PADV;\
            int rpf = ((PF) < 1) ? 1 : (PF);                                 \
            AA = rowbase[(size_t)rpf * RSTR + l];                            \
            EE = (l < 16) ? rowbase[(size_t)rpf * RSTR + 32 + l] : 0.0f;     \
            float bv;                                                        \
            tag = argmax48(s_a, s_b, &bv);                                   \
        }

        for (int t = TT - 1; t >= 3; t -= 3) {   // 1023 steps, divisible by 3
            BT_STEP(t,     a0, e0, t - 3)
            BT_STEP(t - 1, a1, e1, t - 4)
            BT_STEP(t - 2, a2, e2, t - 5)
        }
        if (l == 0) path_sh[0] = (uint8_t)tag;
#undef BT_STEP
    }
    __syncthreads();

    // ---------------- coalesced path dump ----------------
    float* pout = out + BB + (size_t)seq * TT;
    for (int t = tid; t < TT; t += NT) pout[t] = (float)path_sh[t];
}

extern "C" void kernel_launch(void* const* d_in, const int* in_sizes, int n_in,
                              void* d_out, int out_size) {
    (void)in_sizes; (void)n_in; (void)out_size;
    const float* feats = (const float*)d_in[0];
    const float* trans = (const float*)d_in[1];
    float* out = (float*)d_out;
    viterbi_kernel<<<BB, NT>>>(feats, trans, out);
}